// round 1
// baseline (speedup 1.0000x reference)
#include <cuda_runtime.h>
#include <cstdint>

// ATSS assignment: B=16 images, N=30000 preds, G=64 GTs, K=9.
// Outputs (concatenated into float d_out, tuple order, each [B,G,K]):
//   [0,S)    pred_idx  (mask ? k_idx : -1)
//   [S,2S)   gt_idx    (mask ? g : -1)
//   [2S,3S)  mask      (0/1)
//   [3S,4S)  ious
// with S = B*G*K = 9216.

#define B_ 16
#define N_ 30000
#define G_ 64
#define KK 9
#define THREADS 256
#define GT_TILE 4

__device__ __forceinline__ float f_inf() { return __int_as_float(0x7f800000); }

__global__ __launch_bounds__(THREADS) void atss_kernel(
    const float* __restrict__ pred,   // [B, N, 4] cxcywh
    const float* __restrict__ gt,     // [B, G, 4] cxcywh
    float* __restrict__ out)
{
    const int groups_per_img = G_ / GT_TILE;           // 16
    const int img = blockIdx.x / groups_per_img;
    const int g0  = (blockIdx.x % groups_per_img) * GT_TILE;

    const float4* __restrict__ pb = reinterpret_cast<const float4*>(pred) + (size_t)img * N_;
    const float4* __restrict__ gb = reinterpret_cast<const float4*>(gt)   + (size_t)img * G_ + g0;

    float gcx[GT_TILE], gcy[GT_TILE];
#pragma unroll
    for (int t = 0; t < GT_TILE; t++) {
        float4 q = gb[t];
        gcx[t] = q.x; gcy[t] = q.y;
    }

    // Per-thread top-K lists (sorted ascending by (d, idx)). Static indexing only.
    float bd[GT_TILE][KK];
    int   bi[GT_TILE][KK];
    float wg[GT_TILE];   // conservative squared-distance guard
#pragma unroll
    for (int t = 0; t < GT_TILE; t++) {
        wg[t] = f_inf();
#pragma unroll
        for (int k = 0; k < KK; k++) { bd[t][k] = f_inf(); bi[t][k] = 0x7fffffff; }
    }

    for (int i = threadIdx.x; i < N_; i += THREADS) {
        float4 p = pb[i];
#pragma unroll
        for (int t = 0; t < GT_TILE; t++) {
            float dx = __fsub_rn(gcx[t], p.x);
            float dy = __fsub_rn(gcy[t], p.y);
            float d2g = fmaf(dy, dy, dx * dx);     // fast guard value (fma OK here)
            if (d2g <= wg[t]) {
                // Exact path matching JAX: d2 = dx*dx + dy*dy (no fma), d = IEEE sqrt.
                float d2 = __fadd_rn(__fmul_rn(dx, dx), __fmul_rn(dy, dy));
                float d  = __fsqrt_rn(d2);
                // Within a thread, scan index i is strictly increasing, so an
                // equal-d candidate always loses the tie-break: strict <.
                if (d < bd[t][KK - 1]) {
                    bd[t][KK - 1] = d; bi[t][KK - 1] = i;
#pragma unroll
                    for (int k = KK - 1; k > 0; k--) {
                        bool sw = (bd[t][k] < bd[t][k - 1]) ||
                                  (bd[t][k] == bd[t][k - 1] && bi[t][k] < bi[t][k - 1]);
                        if (sw) {
                            float td = bd[t][k]; bd[t][k] = bd[t][k - 1]; bd[t][k - 1] = td;
                            int   ti = bi[t][k]; bi[t][k] = bi[t][k - 1]; bi[t][k - 1] = ti;
                        }
                    }
                    // Conservative guard: d2g <= wg whenever insertion is possible.
                    // mul_ru + 2e-6 inflation covers sqrt rounding + fma guard error.
                    float w = bd[t][KK - 1];
                    wg[t] = __fmul_rn(__fmul_ru(w, w), 1.000002f);
                }
            }
        }
    }

    __shared__ float sd[THREADS * KK];
    __shared__ int   si[THREADS * KK];

    for (int t = 0; t < GT_TILE; t++) {
        // Publish this thread's list for GT t.
#pragma unroll
        for (int k = 0; k < KK; k++) {
            sd[threadIdx.x * KK + k] = bd[t][k];
            si[threadIdx.x * KK + k] = bi[t][k];
        }
        __syncthreads();

        // Tree merge of sorted 9-lists.
        for (int s = THREADS / 2; s >= 1; s >>= 1) {
            if (threadIdx.x < (unsigned)s) {
                int a = threadIdx.x * KK;
                int b = (threadIdx.x + s) * KK;
                float od[KK]; int oi[KK];
                int ia = 0, ib = 0;
#pragma unroll
                for (int k = 0; k < KK; k++) {
                    float da = sd[a + ia], db = sd[b + ib];
                    int   ja = si[a + ia], jb = si[b + ib];
                    bool takeA = (da < db) || (da == db && ja < jb);
                    od[k] = takeA ? da : db;
                    oi[k] = takeA ? ja : jb;
                    if (takeA) ia++; else ib++;
                }
#pragma unroll
                for (int k = 0; k < KK; k++) { sd[a + k] = od[k]; si[a + k] = oi[k]; }
            }
            __syncthreads();
        }

        if (threadIdx.x == 0) {
            const int g = g0 + t;
            float4 q = gb[t];
            // gt cxcywh -> xyxy (match JAX op order: mul then sub/add, no fma)
            float ghw = __fmul_rn(0.5f, q.z);
            float ghh = __fmul_rn(0.5f, q.w);
            float gx1 = __fsub_rn(q.x, ghw), gy1 = __fsub_rn(q.y, ghh);
            float gx2 = __fadd_rn(q.x, ghw), gy2 = __fadd_rn(q.y, ghh);
            float area_g = __fmul_rn(__fsub_rn(gx2, gx1), __fsub_rn(gy2, gy1));

            float iouv[KK], cxk[KK], cyk[KK];
            int   idxk[KK];
#pragma unroll
            for (int k = 0; k < KK; k++) {
                int id = si[k];
                idxk[k] = id;
                float4 p = pb[id];
                cxk[k] = p.x; cyk[k] = p.y;
                float hw = __fmul_rn(0.5f, p.z);
                float hh = __fmul_rn(0.5f, p.w);
                float bx1 = __fsub_rn(p.x, hw), by1 = __fsub_rn(p.y, hh);
                float bx2 = __fadd_rn(p.x, hw), by2 = __fadd_rn(p.y, hh);
                float ltx = fmaxf(gx1, bx1), lty = fmaxf(gy1, by1);
                float rbx = fminf(gx2, bx2), rby = fminf(gy2, by2);
                float w = fmaxf(__fsub_rn(rbx, ltx), 0.0f);
                float h = fmaxf(__fsub_rn(rby, lty), 0.0f);
                float inter = __fmul_rn(w, h);
                float area_b = __fmul_rn(__fsub_rn(bx2, bx1), __fsub_rn(by2, by1));
                float den = __fsub_rn(__fadd_rn(area_g, area_b), inter);
                iouv[k] = __fdiv_rn(inter, den);
            }

            // mean + std (ddof=1), sequential f32 like XLA's small-reduce loop
            float s = 0.0f;
#pragma unroll
            for (int k = 0; k < KK; k++) s = __fadd_rn(s, iouv[k]);
            float mean = __fdiv_rn(s, 9.0f);
            float v = 0.0f;
#pragma unroll
            for (int k = 0; k < KK; k++) {
                float c = __fsub_rn(iouv[k], mean);
                v = __fadd_rn(v, __fmul_rn(c, c));
            }
            float stdv = __fsqrt_rn(__fdiv_rn(v, 8.0f));
            float thr = __fadd_rn(mean, stdv);

            const size_t S = (size_t)B_ * G_ * KK;
            const size_t base = ((size_t)img * G_ + g) * KK;
#pragma unroll
            for (int k = 0; k < KK; k++) {
                bool inside = (gx1 <= cxk[k]) && (cxk[k] <= gx2) &&
                              (gy1 <= cyk[k]) && (cyk[k] <= gy2);
                bool m = (iouv[k] >= thr) && inside;
                out[base + k]          = m ? (float)idxk[k] : -1.0f;
                out[S + base + k]      = m ? (float)g : -1.0f;
                out[2 * S + base + k]  = m ? 1.0f : 0.0f;
                out[3 * S + base + k]  = iouv[k];
            }
        }
        __syncthreads();
    }
}

extern "C" void kernel_launch(void* const* d_in, const int* in_sizes, int n_in,
                              void* d_out, int out_size) {
    const float* pred = (const float*)d_in[0];  // [16,30000,4]
    const float* gt   = (const float*)d_in[1];  // [16,64,4]
    float* out = (float*)d_out;
    dim3 grid(B_ * (G_ / GT_TILE));   // 256 blocks
    atss_kernel<<<grid, THREADS>>>(pred, gt, out);
}

// round 2
// speedup vs baseline: 5.5282x; 5.5282x over previous
#include <cuda_runtime.h>
#include <cstdint>

// ATSS assignment: B=16, N=30000 preds, G=64 GTs, K=9.
// Output (float d_out), tuple order, each [B,G,K], S = 9216:
//   [0,S) pred_idx | [S,2S) gt_idx | [2S,3S) mask | [3S,4S) ious

#define B_ 16
#define N_ 30000
#define G_ 64
#define KK 9
#define NW 4            // warps per block (each scans N/4)
#define GT_TILE 4       // GTs per block (each warp keeps GT_TILE lane-lists)
#define CHUNK (N_ / NW) // 7500
#define FULL 0xffffffffu

__device__ __forceinline__ float f_inf() { return __int_as_float(0x7f800000); }

__global__ __launch_bounds__(NW * 32) void atss_kernel(
    const float* __restrict__ pred,   // [B,N,4] cxcywh
    const float* __restrict__ gt,     // [B,G,4] cxcywh
    float* __restrict__ out)
{
    const int img = blockIdx.x >> 4;             // /16
    const int g0  = (blockIdx.x & 15) * GT_TILE;

    const float4* __restrict__ pb = reinterpret_cast<const float4*>(pred) + (size_t)img * N_;
    const float4* __restrict__ gb = reinterpret_cast<const float4*>(gt)   + (size_t)img * G_ + g0;

    const int w    = threadIdx.x >> 5;
    const int lane = threadIdx.x & 31;
    const int cbeg = w * CHUNK;
    const int cend = cbeg + CHUNK;

    float gcx[GT_TILE], gcy[GT_TILE];
#pragma unroll
    for (int t = 0; t < GT_TILE; t++) {
        float4 q = gb[t];
        gcx[t] = q.x; gcy[t] = q.y;
    }

    // Warp-distributed sorted top-9 per GT: lane k (k<9) holds element k, ascending (d,i).
    float ld[GT_TILE]; int li[GT_TILE]; float wg2[GT_TILE];
#pragma unroll
    for (int t = 0; t < GT_TILE; t++) { ld[t] = f_inf(); li[t] = 0x7fffffff; wg2[t] = f_inf(); }

    const int NMIT = (CHUNK + 4 * 32 - 1) / (4 * 32);   // 59 macro-iterations
    for (int mit = 0; mit < NMIT; mit++) {
        const int i0 = cbeg + mit * 128 + lane;
        float4 p[4]; int ii[4]; bool v[4];
        // Issue 4 coalesced loads up front (MLP=4).
#pragma unroll
        for (int j = 0; j < 4; j++) {
            ii[j] = i0 + j * 32;
            v[j]  = ii[j] < cend;
            p[j]  = pb[v[j] ? ii[j] : cbeg];
        }
#pragma unroll
        for (int j = 0; j < 4; j++) {
            bool q[GT_TILE];
            bool anyq = false;
#pragma unroll
            for (int t = 0; t < GT_TILE; t++) {
                float dx = gcx[t] - p[j].x;
                float dy = gcy[t] - p[j].y;
                float d2g = __fmaf_rn(dx, dx, dy * dy);   // fast guard; inflation covers error
                q[t] = v[j] && (d2g <= wg2[t]);
                anyq |= q[t];
            }
            if (__any_sync(FULL, anyq)) {
#pragma unroll
                for (int t = 0; t < GT_TILE; t++) {
                    unsigned m = __ballot_sync(FULL, q[t]);
                    if (m) {
                        // Exact distance, matching JAX: rn mul/add then IEEE sqrt.
                        float dx = __fsub_rn(gcx[t], p[j].x);
                        float dy = __fsub_rn(gcy[t], p[j].y);
                        float de = __fsqrt_rn(__fadd_rn(__fmul_rn(dx, dx), __fmul_rn(dy, dy)));
                        while (m) {
                            int src = __ffs(m) - 1; m &= m - 1;
                            float dv = __shfl_sync(FULL, de, src);
                            int   iv = __shfl_sync(FULL, ii[j], src);
                            // Insert (dv,iv) into the lane-distributed sorted list.
                            bool ogt = (ld[t] > dv) || (ld[t] == dv && li[t] > iv);
                            unsigned bgt = __ballot_sync(FULL, ogt);
                            int pos = __popc(~bgt & 0x1FFu);   // #old <= new among lanes 0..8
                            float pd = __shfl_up_sync(FULL, ld[t], 1);
                            int   pi = __shfl_up_sync(FULL, li[t], 1);
                            if (lane <= 8) {
                                if (lane == pos)      { ld[t] = dv; li[t] = iv; }
                                else if (lane > pos)  { ld[t] = pd; li[t] = pi; }
                            }
                        }
                        float d8 = __shfl_sync(FULL, ld[t], 8);
                        wg2[t] = __fmul_rn(__fmul_ru(d8, d8), 1.000002f);
                    }
                }
            }
        }
    }

    // Publish per-warp lists, then one thread per GT merges + epilogue.
    __shared__ float sd[NW][GT_TILE][KK];
    __shared__ int   si[NW][GT_TILE][KK];
    if (lane < KK) {
#pragma unroll
        for (int t = 0; t < GT_TILE; t++) { sd[w][t][lane] = ld[t]; si[w][t][lane] = li[t]; }
    }
    __syncthreads();

    if (threadIdx.x < GT_TILE) {
        const int t = threadIdx.x;
        const int g = g0 + t;

        // 4-way merge of sorted 9-lists -> global top-9 (ascending (d,i)).
        int ptr[NW] = {0, 0, 0, 0};
        int   idxk[KK];
        float cxk[KK], cyk[KK];
#pragma unroll
        for (int k = 0; k < KK; k++) {
            float bestd = f_inf(); int besti = 0x7fffffff; int bw = 0;
#pragma unroll
            for (int u = 0; u < NW; u++) {
                float du = (ptr[u] < KK) ? sd[u][t][ptr[u]] : f_inf();
                int   ju = (ptr[u] < KK) ? si[u][t][ptr[u]] : 0x7fffffff;
                bool take = (du < bestd) || (du == bestd && ju < besti);
                if (take) { bestd = du; besti = ju; bw = u; }
            }
            ptr[bw]++;
            idxk[k] = besti;
        }

        // GT box -> xyxy (exact rn ops, same order as JAX).
        float4 qg = gb[t];
        float ghw = __fmul_rn(0.5f, qg.z);
        float ghh = __fmul_rn(0.5f, qg.w);
        float gx1 = __fsub_rn(qg.x, ghw), gy1 = __fsub_rn(qg.y, ghh);
        float gx2 = __fadd_rn(qg.x, ghw), gy2 = __fadd_rn(qg.y, ghh);
        float area_g = __fmul_rn(__fsub_rn(gx2, gx1), __fsub_rn(gy2, gy1));

        float iouv[KK];
#pragma unroll
        for (int k = 0; k < KK; k++) {
            float4 p = pb[idxk[k]];
            cxk[k] = p.x; cyk[k] = p.y;
            float hw = __fmul_rn(0.5f, p.z);
            float hh = __fmul_rn(0.5f, p.w);
            float bx1 = __fsub_rn(p.x, hw), by1 = __fsub_rn(p.y, hh);
            float bx2 = __fadd_rn(p.x, hw), by2 = __fadd_rn(p.y, hh);
            float ltx = fmaxf(gx1, bx1), lty = fmaxf(gy1, by1);
            float rbx = fminf(gx2, bx2), rby = fminf(gy2, by2);
            float wd = fmaxf(__fsub_rn(rbx, ltx), 0.0f);
            float ht = fmaxf(__fsub_rn(rby, lty), 0.0f);
            float inter = __fmul_rn(wd, ht);
            float area_b = __fmul_rn(__fsub_rn(bx2, bx1), __fsub_rn(by2, by1));
            float den = __fsub_rn(__fadd_rn(area_g, area_b), inter);
            iouv[k] = __fdiv_rn(inter, den);
        }

        // mean + std (ddof=1), sequential f32.
        float s = 0.0f;
#pragma unroll
        for (int k = 0; k < KK; k++) s = __fadd_rn(s, iouv[k]);
        float mean = __fdiv_rn(s, 9.0f);
        float vv = 0.0f;
#pragma unroll
        for (int k = 0; k < KK; k++) {
            float c = __fsub_rn(iouv[k], mean);
            vv = __fadd_rn(vv, __fmul_rn(c, c));
        }
        float thr = __fadd_rn(mean, __fsqrt_rn(__fdiv_rn(vv, 8.0f)));

        const size_t S = (size_t)B_ * G_ * KK;
        const size_t base = ((size_t)img * G_ + g) * KK;
#pragma unroll
        for (int k = 0; k < KK; k++) {
            bool inside = (gx1 <= cxk[k]) && (cxk[k] <= gx2) &&
                          (gy1 <= cyk[k]) && (cyk[k] <= gy2);
            bool msk = (iouv[k] >= thr) && inside;
            out[base + k]         = msk ? (float)idxk[k] : -1.0f;
            out[S + base + k]     = msk ? (float)g : -1.0f;
            out[2 * S + base + k] = msk ? 1.0f : 0.0f;
            out[3 * S + base + k] = iouv[k];
        }
    }
}

extern "C" void kernel_launch(void* const* d_in, const int* in_sizes, int n_in,
                              void* d_out, int out_size) {
    const float* pred = (const float*)d_in[0];  // [16,30000,4]
    const float* gt   = (const float*)d_in[1];  // [16,64,4]
    float* out = (float*)d_out;
    dim3 grid(B_ * (G_ / GT_TILE));   // 256 blocks x 128 threads
    atss_kernel<<<grid, NW * 32>>>(pred, gt, out);
}

// round 3
// speedup vs baseline: 5.7684x; 1.0434x over previous
#include <cuda_runtime.h>
#include <cstdint>

// ATSS assignment: B=16, N=30000 preds, G=64 GTs, K=9.
// Output (float d_out), tuple order, each [B,G,K], S = 9216:
//   [0,S) pred_idx | [S,2S) gt_idx | [2S,3S) mask | [3S,4S) ious

#define B_ 16
#define N_ 30000
#define G_ 64
#define KK 9
#define NW 16            // warps per block (each scans N/16 = 1875)
#define GT_TILE 4        // GTs per block
#define CHUNK (N_ / NW)  // 1875
#define FULL 0xffffffffu

__device__ __forceinline__ float f_inf() { return __int_as_float(0x7f800000); }

__global__ __launch_bounds__(NW * 32) void atss_kernel(
    const float* __restrict__ pred,   // [B,N,4] cxcywh
    const float* __restrict__ gt,     // [B,G,4] cxcywh
    float* __restrict__ out)
{
    const int img = blockIdx.x >> 4;             // /16
    const int g0  = (blockIdx.x & 15) * GT_TILE;

    const float4* __restrict__ pb = reinterpret_cast<const float4*>(pred) + (size_t)img * N_;
    const float4* __restrict__ gb = reinterpret_cast<const float4*>(gt)   + (size_t)img * G_ + g0;

    const int w    = threadIdx.x >> 5;
    const int lane = threadIdx.x & 31;
    const int cbeg = w * CHUNK;
    const int cend = cbeg + CHUNK;

    float gcx[GT_TILE], gcy[GT_TILE];
#pragma unroll
    for (int t = 0; t < GT_TILE; t++) {
        float4 q = gb[t];
        gcx[t] = q.x; gcy[t] = q.y;
    }

    // Warp-distributed sorted top-9 per GT: lane k (k<9) holds element k, ascending (d,i).
    float ld[GT_TILE]; int li[GT_TILE]; float wg2[GT_TILE];
#pragma unroll
    for (int t = 0; t < GT_TILE; t++) { ld[t] = f_inf(); li[t] = 0x7fffffff; wg2[t] = f_inf(); }

    const int NMIT = (CHUNK + 4 * 32 - 1) / (4 * 32);   // 15 macro-iterations
    for (int mit = 0; mit < NMIT; mit++) {
        const int i0 = cbeg + mit * 128 + lane;
        float4 p[4]; int ii[4]; bool v[4];
        // Issue 4 coalesced loads up front (MLP=4).
#pragma unroll
        for (int j = 0; j < 4; j++) {
            ii[j] = i0 + j * 32;
            v[j]  = ii[j] < cend;
            p[j]  = pb[v[j] ? ii[j] : cbeg];
        }
#pragma unroll
        for (int j = 0; j < 4; j++) {
            bool q[GT_TILE];
            bool anyq = false;
#pragma unroll
            for (int t = 0; t < GT_TILE; t++) {
                float dx = gcx[t] - p[j].x;
                float dy = gcy[t] - p[j].y;
                float d2g = __fmaf_rn(dx, dx, dy * dy);   // fast guard; inflation covers error
                q[t] = v[j] && (d2g <= wg2[t]);
                anyq |= q[t];
            }
            if (__any_sync(FULL, anyq)) {
#pragma unroll
                for (int t = 0; t < GT_TILE; t++) {
                    unsigned m = __ballot_sync(FULL, q[t]);
                    if (m) {
                        // Exact distance, matching JAX: rn mul/add then IEEE sqrt.
                        float dx = __fsub_rn(gcx[t], p[j].x);
                        float dy = __fsub_rn(gcy[t], p[j].y);
                        float de = __fsqrt_rn(__fadd_rn(__fmul_rn(dx, dx), __fmul_rn(dy, dy)));
                        while (m) {
                            int src = __ffs(m) - 1; m &= m - 1;
                            float dv = __shfl_sync(FULL, de, src);
                            int   iv = __shfl_sync(FULL, ii[j], src);
                            // Insert (dv,iv) into the lane-distributed sorted list.
                            bool ogt = (ld[t] > dv) || (ld[t] == dv && li[t] > iv);
                            unsigned bgt = __ballot_sync(FULL, ogt);
                            int pos = __popc(~bgt & 0x1FFu);   // #old <= new among lanes 0..8
                            float pd = __shfl_up_sync(FULL, ld[t], 1);
                            int   pi = __shfl_up_sync(FULL, li[t], 1);
                            if (lane <= 8) {
                                if (lane == pos)      { ld[t] = dv; li[t] = iv; }
                                else if (lane > pos)  { ld[t] = pd; li[t] = pi; }
                            }
                        }
                        float d8 = __shfl_sync(FULL, ld[t], 8);
                        wg2[t] = __fmul_rn(__fmul_ru(d8, d8), 1.000002f);
                    }
                }
            }
        }
    }

    // Publish per-warp lists.
    __shared__ float sd[NW][GT_TILE][KK];
    __shared__ int   si[NW][GT_TILE][KK];
    if (lane < KK) {
#pragma unroll
        for (int t = 0; t < GT_TILE; t++) { sd[w][t][lane] = ld[t]; si[w][t][lane] = li[t]; }
    }
    __syncthreads();

    // Tree merge over the NW dimension; GTs handled by parallel threads.
    for (int s = NW / 2; s >= 1; s >>= 1) {
        if (threadIdx.x < (unsigned)(s * GT_TILE)) {
            const int u = threadIdx.x >> 2;      // /GT_TILE
            const int t = threadIdx.x & 3;
            float od[KK]; int oi[KK];
            int ia = 0, ib = 0;
#pragma unroll
            for (int k = 0; k < KK; k++) {
                float da = sd[u][t][ia],     db = sd[u + s][t][ib];
                int   ja = si[u][t][ia],     jb = si[u + s][t][ib];
                bool ta = (da < db) || (da == db && ja < jb);
                od[k] = ta ? da : db;
                oi[k] = ta ? ja : jb;
                if (ta) ia++; else ib++;
            }
#pragma unroll
            for (int k = 0; k < KK; k++) { sd[u][t][k] = od[k]; si[u][t][k] = oi[k]; }
        }
        __syncthreads();
    }

    if (threadIdx.x < GT_TILE) {
        const int t = threadIdx.x;
        const int g = g0 + t;

        int idxk[KK];
#pragma unroll
        for (int k = 0; k < KK; k++) idxk[k] = si[0][t][k];

        // GT box -> xyxy (exact rn ops, same order as JAX).
        float4 qg = gb[t];
        float ghw = __fmul_rn(0.5f, qg.z);
        float ghh = __fmul_rn(0.5f, qg.w);
        float gx1 = __fsub_rn(qg.x, ghw), gy1 = __fsub_rn(qg.y, ghh);
        float gx2 = __fadd_rn(qg.x, ghw), gy2 = __fadd_rn(qg.y, ghh);
        float area_g = __fmul_rn(__fsub_rn(gx2, gx1), __fsub_rn(gy2, gy1));

        float iouv[KK], cxk[KK], cyk[KK];
#pragma unroll
        for (int k = 0; k < KK; k++) {
            float4 p = pb[idxk[k]];
            cxk[k] = p.x; cyk[k] = p.y;
            float hw = __fmul_rn(0.5f, p.z);
            float hh = __fmul_rn(0.5f, p.w);
            float bx1 = __fsub_rn(p.x, hw), by1 = __fsub_rn(p.y, hh);
            float bx2 = __fadd_rn(p.x, hw), by2 = __fadd_rn(p.y, hh);
            float ltx = fmaxf(gx1, bx1), lty = fmaxf(gy1, by1);
            float rbx = fminf(gx2, bx2), rby = fminf(gy2, by2);
            float wd = fmaxf(__fsub_rn(rbx, ltx), 0.0f);
            float ht = fmaxf(__fsub_rn(rby, lty), 0.0f);
            float inter = __fmul_rn(wd, ht);
            float area_b = __fmul_rn(__fsub_rn(bx2, bx1), __fsub_rn(by2, by1));
            float den = __fsub_rn(__fadd_rn(area_g, area_b), inter);
            iouv[k] = __fdiv_rn(inter, den);
        }

        // mean + std (ddof=1), sequential f32.
        float s = 0.0f;
#pragma unroll
        for (int k = 0; k < KK; k++) s = __fadd_rn(s, iouv[k]);
        float mean = __fdiv_rn(s, 9.0f);
        float vv = 0.0f;
#pragma unroll
        for (int k = 0; k < KK; k++) {
            float c = __fsub_rn(iouv[k], mean);
            vv = __fadd_rn(vv, __fmul_rn(c, c));
        }
        float thr = __fadd_rn(mean, __fsqrt_rn(__fdiv_rn(vv, 8.0f)));

        const size_t S = (size_t)B_ * G_ * KK;
        const size_t base = ((size_t)img * G_ + g) * KK;
#pragma unroll
        for (int k = 0; k < KK; k++) {
            bool inside = (gx1 <= cxk[k]) && (cxk[k] <= gx2) &&
                          (gy1 <= cyk[k]) && (cyk[k] <= gy2);
            bool msk = (iouv[k] >= thr) && inside;
            out[base + k]         = msk ? (float)idxk[k] : -1.0f;
            out[S + base + k]     = msk ? (float)g : -1.0f;
            out[2 * S + base + k] = msk ? 1.0f : 0.0f;
            out[3 * S + base + k] = iouv[k];
        }
    }
}

extern "C" void kernel_launch(void* const* d_in, const int* in_sizes, int n_in,
                              void* d_out, int out_size) {
    const float* pred = (const float*)d_in[0];  // [16,30000,4]
    const float* gt   = (const float*)d_in[1];  // [16,64,4]
    float* out = (float*)d_out;
    dim3 grid(B_ * (G_ / GT_TILE));   // 256 blocks x 512 threads
    atss_kernel<<<grid, NW * 32>>>(pred, gt, out);
}

// round 4
// speedup vs baseline: 9.4486x; 1.6380x over previous
#include <cuda_runtime.h>
#include <cstdint>

// ATSS assignment: B=16, N=30000 preds, G=64 GTs, K=9.
// Output (float d_out), tuple order, each [B,G,K], S = 9216:
//   [0,S) pred_idx | [S,2S) gt_idx | [2S,3S) mask | [3S,4S) ious

#define B_ 16
#define N_ 30000
#define G_ 64
#define KK 9
#define NW 16            // warps per block
#define GT_TILE 8        // GTs per block
#define CHUNK (N_ / NW)  // 1875
#define FULL 0xffffffffu
#define NBLK (B_ * (G_ / GT_TILE))   // 128 blocks

// Radius pre-filter. Uniform data: 9th-nearest ~0.0098, so r=0.04 holds ~150
// candidates/GT (worst-case corner GT lambda~38, P(<9) ~ 4e-9). Correctness
// does NOT depend on this: validity check + exact fallback below.
#define RADIUS 0.04f
#define R2G   (RADIUS * RADIUS * 1.000002f)   // guard compare (covers fma error)
#define R2CHK (RADIUS * RADIUS * 0.999998f)   // validity: d9^2 must be < this

__device__ int g_bad[NBLK];

__device__ __forceinline__ float f_inf() { return __int_as_float(0x7f800000); }

__device__ __forceinline__ void atss_block(
    const float4* __restrict__ pb, const float4* __restrict__ gb,
    float* __restrict__ out, int img, int g0, float ginit, bool main_pass)
{
    const int w    = threadIdx.x >> 5;
    const int lane = threadIdx.x & 31;
    const int cbeg = w * CHUNK;
    const int cend = cbeg + CHUNK;

    float gcx[GT_TILE], gcy[GT_TILE];
#pragma unroll
    for (int t = 0; t < GT_TILE; t++) {
        float4 q = gb[t];
        gcx[t] = q.x; gcy[t] = q.y;
    }

    // Warp-distributed sorted top-9 per GT: lane k (k<9) holds elem k, asc (d,i).
    float ld[GT_TILE]; int li[GT_TILE]; float wg2[GT_TILE];
#pragma unroll
    for (int t = 0; t < GT_TILE; t++) { ld[t] = f_inf(); li[t] = 0x7fffffff; wg2[t] = ginit; }

    const int NMIT = (CHUNK + 4 * 32 - 1) / (4 * 32);   // 15
    for (int mit = 0; mit < NMIT; mit++) {
        const int i0 = cbeg + mit * 128 + lane;
        float4 p[4]; int ii[4]; bool v[4];
#pragma unroll
        for (int j = 0; j < 4; j++) {           // MLP=4 coalesced loads
            ii[j] = i0 + j * 32;
            v[j]  = ii[j] < cend;
            p[j]  = pb[v[j] ? ii[j] : cbeg];
        }
#pragma unroll
        for (int j = 0; j < 4; j++) {
            bool q[GT_TILE];
            bool anyq = false;
#pragma unroll
            for (int t = 0; t < GT_TILE; t++) {
                float dx = gcx[t] - p[j].x;
                float dy = gcy[t] - p[j].y;
                float d2g = __fmaf_rn(dx, dx, dy * dy);
                q[t] = v[j] && (d2g <= wg2[t]);
                anyq |= q[t];
            }
            if (__any_sync(FULL, anyq)) {
#pragma unroll
                for (int t = 0; t < GT_TILE; t++) {
                    unsigned m = __ballot_sync(FULL, q[t]);
                    if (m) {
                        // Exact distance matching JAX: rn mul/add then IEEE sqrt.
                        float dx = __fsub_rn(gcx[t], p[j].x);
                        float dy = __fsub_rn(gcy[t], p[j].y);
                        float de = __fsqrt_rn(__fadd_rn(__fmul_rn(dx, dx), __fmul_rn(dy, dy)));
                        while (m) {
                            int src = __ffs(m) - 1; m &= m - 1;
                            float dv = __shfl_sync(FULL, de, src);
                            int   iv = __shfl_sync(FULL, ii[j], src);
                            bool ogt = (ld[t] > dv) || (ld[t] == dv && li[t] > iv);
                            unsigned bgt = __ballot_sync(FULL, ogt);
                            int pos = __popc(~bgt & 0x1FFu);
                            float pd = __shfl_up_sync(FULL, ld[t], 1);
                            int   pi = __shfl_up_sync(FULL, li[t], 1);
                            if (lane <= 8) {
                                if (lane == pos)      { ld[t] = dv; li[t] = iv; }
                                else if (lane > pos)  { ld[t] = pd; li[t] = pi; }
                            }
                        }
                        float d8 = __shfl_sync(FULL, ld[t], 8);
                        float ng = __fmul_rn(__fmul_ru(d8, d8), 1.000002f);
                        wg2[t] = fminf(wg2[t], ng);
                    }
                }
            }
        }
    }

    __shared__ float sd[NW][GT_TILE][KK];
    __shared__ int   si[NW][GT_TILE][KK];
    __shared__ int   s_ok[GT_TILE];
    if (lane < KK) {
#pragma unroll
        for (int t = 0; t < GT_TILE; t++) { sd[w][t][lane] = ld[t]; si[w][t][lane] = li[t]; }
    }
    __syncthreads();

    // Tree merge over warps; (u, t) pairs in parallel threads.
    for (int s = NW / 2; s >= 1; s >>= 1) {
        if (threadIdx.x < (unsigned)(s * GT_TILE)) {
            const int u = threadIdx.x >> 3;
            const int t = threadIdx.x & 7;
            float od[KK]; int oi[KK];
            int ia = 0, ib = 0;
#pragma unroll
            for (int k = 0; k < KK; k++) {
                float da = sd[u][t][ia], db = sd[u + s][t][ib];
                int   ja = si[u][t][ia], jb = si[u + s][t][ib];
                bool ta = (da < db) || (da == db && ja < jb);
                od[k] = ta ? da : db;
                oi[k] = ta ? ja : jb;
                if (ta) ia++; else ib++;
            }
#pragma unroll
            for (int k = 0; k < KK; k++) { sd[u][t][k] = od[k]; si[u][t][k] = oi[k]; }
        }
        __syncthreads();
    }

    if (threadIdx.x < GT_TILE) {
        const int t = threadIdx.x;
        const int g = g0 + t;

        int   i8 = si[0][t][KK - 1];
        float d8 = sd[0][t][KK - 1];
        // Validity: every guard-excluded pred provably has d > r*(1-eps);
        // if found 9th is strictly inside, the radius scan top-9 == full top-9.
        bool ok = main_pass ? (i8 != 0x7fffffff && __fmul_rn(d8, d8) < R2CHK) : true;
        s_ok[t] = ok ? 1 : 0;

        if (ok) {
            int idxk[KK];
#pragma unroll
            for (int k = 0; k < KK; k++) idxk[k] = si[0][t][k];

            float4 qg = gb[t];
            float ghw = __fmul_rn(0.5f, qg.z);
            float ghh = __fmul_rn(0.5f, qg.w);
            float gx1 = __fsub_rn(qg.x, ghw), gy1 = __fsub_rn(qg.y, ghh);
            float gx2 = __fadd_rn(qg.x, ghw), gy2 = __fadd_rn(qg.y, ghh);
            float area_g = __fmul_rn(__fsub_rn(gx2, gx1), __fsub_rn(gy2, gy1));

            float iouv[KK], cxk[KK], cyk[KK];
#pragma unroll
            for (int k = 0; k < KK; k++) {
                float4 p = pb[idxk[k]];
                cxk[k] = p.x; cyk[k] = p.y;
                float hw = __fmul_rn(0.5f, p.z);
                float hh = __fmul_rn(0.5f, p.w);
                float bx1 = __fsub_rn(p.x, hw), by1 = __fsub_rn(p.y, hh);
                float bx2 = __fadd_rn(p.x, hw), by2 = __fadd_rn(p.y, hh);
                float ltx = fmaxf(gx1, bx1), lty = fmaxf(gy1, by1);
                float rbx = fminf(gx2, bx2), rby = fminf(gy2, by2);
                float wd = fmaxf(__fsub_rn(rbx, ltx), 0.0f);
                float ht = fmaxf(__fsub_rn(rby, lty), 0.0f);
                float inter = __fmul_rn(wd, ht);
                float area_b = __fmul_rn(__fsub_rn(bx2, bx1), __fsub_rn(by2, by1));
                float den = __fsub_rn(__fadd_rn(area_g, area_b), inter);
                iouv[k] = __fdiv_rn(inter, den);
            }

            float s = 0.0f;
#pragma unroll
            for (int k = 0; k < KK; k++) s = __fadd_rn(s, iouv[k]);
            float mean = __fdiv_rn(s, 9.0f);
            float vv = 0.0f;
#pragma unroll
            for (int k = 0; k < KK; k++) {
                float c = __fsub_rn(iouv[k], mean);
                vv = __fadd_rn(vv, __fmul_rn(c, c));
            }
            float thr = __fadd_rn(mean, __fsqrt_rn(__fdiv_rn(vv, 8.0f)));

            const size_t S = (size_t)B_ * G_ * KK;
            const size_t base = ((size_t)img * G_ + g) * KK;
#pragma unroll
            for (int k = 0; k < KK; k++) {
                bool inside = (gx1 <= cxk[k]) && (cxk[k] <= gx2) &&
                              (gy1 <= cyk[k]) && (cyk[k] <= gy2);
                bool msk = (iouv[k] >= thr) && inside;
                out[base + k]         = msk ? (float)idxk[k] : -1.0f;
                out[S + base + k]     = msk ? (float)g : -1.0f;
                out[2 * S + base + k] = msk ? 1.0f : 0.0f;
                out[3 * S + base + k] = iouv[k];
            }
        }
    }
    __syncthreads();
    if (main_pass && threadIdx.x == 0) {
        int bad = 0;
#pragma unroll
        for (int t = 0; t < GT_TILE; t++) bad |= (s_ok[t] == 0);
        g_bad[blockIdx.x] = bad;
    }
}

__global__ __launch_bounds__(NW * 32) void atss_main(
    const float* __restrict__ pred, const float* __restrict__ gt,
    float* __restrict__ out)
{
    const int img = blockIdx.x >> 3;
    const int g0  = (blockIdx.x & 7) * GT_TILE;
    const float4* pb = reinterpret_cast<const float4*>(pred) + (size_t)img * N_;
    const float4* gb = reinterpret_cast<const float4*>(gt)   + (size_t)img * G_ + g0;
    atss_block(pb, gb, out, img, g0, R2G, true);
}

__global__ __launch_bounds__(NW * 32) void atss_fallback(
    const float* __restrict__ pred, const float* __restrict__ gt,
    float* __restrict__ out)
{
    if (g_bad[blockIdx.x] == 0) return;   // uniform across block
    const int img = blockIdx.x >> 3;
    const int g0  = (blockIdx.x & 7) * GT_TILE;
    const float4* pb = reinterpret_cast<const float4*>(pred) + (size_t)img * N_;
    const float4* gb = reinterpret_cast<const float4*>(gt)   + (size_t)img * G_ + g0;
    atss_block(pb, gb, out, img, g0, f_inf(), false);
}

extern "C" void kernel_launch(void* const* d_in, const int* in_sizes, int n_in,
                              void* d_out, int out_size) {
    const float* pred = (const float*)d_in[0];  // [16,30000,4]
    const float* gt   = (const float*)d_in[1];  // [16,64,4]
    float* out = (float*)d_out;
    atss_main<<<NBLK, NW * 32>>>(pred, gt, out);
    atss_fallback<<<NBLK, NW * 32>>>(pred, gt, out);
}

// round 5
// speedup vs baseline: 11.7726x; 1.2460x over previous
#include <cuda_runtime.h>
#include <cstdint>

// ATSS: B=16, N=30000, G=64, K=9.
// Out (float), tuple order, each [B,G,K], S=9216:
//   [0,S) pred_idx | [S,2S) gt_idx | [2S,3S) mask | [3S,4S) ious

#define B_ 16
#define N_ 30000
#define G_ 64
#define KK 9
#define FULL 0xffffffffu
#define CAP 256

// Radius pre-filter (uniform data: 9th-NN ~0.0098; r=0.04 -> ~150 cands/GT).
// Correctness never depends on it: certificate + inline exact fallback.
#define RADIUS 0.04f
#define R2G   (RADIUS * RADIUS * 1.000002f)   // compaction guard (covers fma err)
#define R2CHK (RADIUS * RADIUS * 0.999998f)   // certificate: exact d9^2 must be < this

__device__ int d_cnt[B_ * G_];            // zero at load; B resets after reading
__device__ int d_cand[B_ * G_ * CAP];

__device__ __forceinline__ float f_inf() { return __int_as_float(0x7f800000); }

// ---------------- Phase A: candidate compaction ----------------
__global__ __launch_bounds__(512) void atss_compact(
    const float* __restrict__ pred, const float* __restrict__ gt)
{
    const int img   = blockIdx.x >> 4;     // 16 slices per image
    const int slice = blockIdx.x & 15;

    __shared__ float2 sg[G_];
    if (threadIdx.x < G_) {
        float4 q = reinterpret_cast<const float4*>(gt)[img * G_ + threadIdx.x];
        sg[threadIdx.x] = make_float2(q.x, q.y);
    }
    __syncthreads();

    const float2* __restrict__ pb2 =
        reinterpret_cast<const float2*>(pred) + (size_t)img * N_ * 2;
    const int sbeg = slice * (N_ / 16);
    const int send = sbeg + (N_ / 16);

    for (int i = sbeg + (int)threadIdx.x; i < send; i += 512) {
        float2 p = pb2[2 * i];            // center only (half the sectors)
        unsigned m0 = 0, m1 = 0;
#pragma unroll
        for (int j = 0; j < 32; j++) {
            float dx = sg[j].x - p.x, dy = sg[j].y - p.y;
            if (__fmaf_rn(dx, dx, dy * dy) <= R2G) m0 |= (1u << j);
        }
#pragma unroll
        for (int j = 0; j < 32; j++) {
            float dx = sg[j + 32].x - p.x, dy = sg[j + 32].y - p.y;
            if (__fmaf_rn(dx, dx, dy * dy) <= R2G) m1 |= (1u << j);
        }
        while (m0) {
            int g = __ffs(m0) - 1; m0 &= m0 - 1;
            int pos = atomicAdd(&d_cnt[img * G_ + g], 1);
            if (pos < CAP) d_cand[(img * G_ + g) * CAP + pos] = i;
        }
        while (m1) {
            int g = __ffs(m1) + 31; m1 &= m1 - 1;
            int pos = atomicAdd(&d_cnt[img * G_ + g], 1);
            if (pos < CAP) d_cand[(img * G_ + g) * CAP + pos] = i;
        }
    }
}

// Lane-distributed sorted top-9 insertion (lanes 0..8 hold list asc by (d,i)).
__device__ __forceinline__ void insert_batch(
    float de, int idx, bool v, float& ldv, int& liv, int lane)
{
    float d8 = __shfl_sync(FULL, ldv, 8);
    int   i8 = __shfl_sync(FULL, liv, 8);
    bool q = v && ((de < d8) || (de == d8 && idx < i8));
    unsigned m = __ballot_sync(FULL, q);
    while (m) {
        int src = __ffs(m) - 1; m &= m - 1;
        float dv = __shfl_sync(FULL, de, src);
        int   iv = __shfl_sync(FULL, idx, src);
        bool ogt = (ldv > dv) || (ldv == dv && liv > iv);
        unsigned bgt = __ballot_sync(FULL, ogt);
        int pos = __popc(~bgt & 0x1FFu);   // #old <= new among lanes 0..8
        float pd = __shfl_up_sync(FULL, ldv, 1);
        int   pi = __shfl_up_sync(FULL, liv, 1);
        if (lane <= 8) {
            if (lane == pos)     { ldv = dv; liv = iv; }
            else if (lane > pos) { ldv = pd; liv = pi; }
        }
    }
}

// ---------------- Phase B: per-GT top-9 + epilogue ----------------
__global__ __launch_bounds__(512) void atss_assign(
    const float* __restrict__ pred, const float* __restrict__ gt,
    float* __restrict__ out)
{
    const int warp = (blockIdx.x << 4) + (threadIdx.x >> 5);  // 0..1023
    const int img  = warp >> 6;
    const int g    = warp & 63;
    const int lane = threadIdx.x & 31;

    const float4* __restrict__ pb  = reinterpret_cast<const float4*>(pred) + (size_t)img * N_;
    const float2* __restrict__ pb2 = reinterpret_cast<const float2*>(pred) + (size_t)img * N_ * 2;
    float4 qg = reinterpret_cast<const float4*>(gt)[img * G_ + g];

    int c = d_cnt[img * G_ + g];
    if (lane == 0) d_cnt[img * G_ + g] = 0;      // self-reset for next replay
    const int* __restrict__ cl = &d_cand[(img * G_ + g) * CAP];

    float ldv = f_inf(); int liv = 0x7fffffff;
    bool ok = (c >= KK && c <= CAP);
    if (ok) {
        for (int b = 0; b < c; b += 32) {
            int k = b + lane; bool v = k < c;
            int idx = v ? cl[k] : 0;
            float2 p = pb2[2 * idx];
            // exact distance matching JAX: rn sub/mul/add then IEEE sqrt
            float dx = __fsub_rn(qg.x, p.x), dy = __fsub_rn(qg.y, p.y);
            float de = __fsqrt_rn(__fadd_rn(__fmul_rn(dx, dx), __fmul_rn(dy, dy)));
            insert_batch(de, idx, v, ldv, liv, lane);
        }
        float d8 = __shfl_sync(FULL, ldv, 8);
        int   i8 = __shfl_sync(FULL, liv, 8);
        // Certificate: excluded preds provably have d^2 > R2CHK, so a strictly
        // inside 9th proves candidate top-9 == exact top-9.
        ok = (i8 != 0x7fffffff) && (__fmul_rn(d8, d8) < R2CHK);
    }
    if (!ok) {   // exact full scan (deterministic, same arithmetic)
        ldv = f_inf(); liv = 0x7fffffff;
        for (int b = 0; b < N_; b += 32) {
            int idx = b + lane; bool v = idx < N_;
            float2 p = pb2[2 * (v ? idx : 0)];
            float dx = __fsub_rn(qg.x, p.x), dy = __fsub_rn(qg.y, p.y);
            float de = __fsqrt_rn(__fadd_rn(__fmul_rn(dx, dx), __fmul_rn(dy, dy)));
            insert_batch(de, idx, v, ldv, liv, lane);
        }
    }

    // ---- epilogue: lanes 0..8 in parallel, exact rn ops ----
    float ghw = __fmul_rn(0.5f, qg.z), ghh = __fmul_rn(0.5f, qg.w);
    float gx1 = __fsub_rn(qg.x, ghw), gy1 = __fsub_rn(qg.y, ghh);
    float gx2 = __fadd_rn(qg.x, ghw), gy2 = __fadd_rn(qg.y, ghh);
    float area_g = __fmul_rn(__fsub_rn(gx2, gx1), __fsub_rn(gy2, gy1));

    float iou = 0.0f, cx = 0.0f, cy = 0.0f;
    int myidx = liv;
    if (lane < KK) {
        float4 p = pb[myidx];
        cx = p.x; cy = p.y;
        float hw = __fmul_rn(0.5f, p.z), hh = __fmul_rn(0.5f, p.w);
        float bx1 = __fsub_rn(p.x, hw), by1 = __fsub_rn(p.y, hh);
        float bx2 = __fadd_rn(p.x, hw), by2 = __fadd_rn(p.y, hh);
        float ltx = fmaxf(gx1, bx1), lty = fmaxf(gy1, by1);
        float rbx = fminf(gx2, bx2), rby = fminf(gy2, by2);
        float wd = fmaxf(__fsub_rn(rbx, ltx), 0.0f);
        float ht = fmaxf(__fsub_rn(rby, lty), 0.0f);
        float inter = __fmul_rn(wd, ht);
        float area_b = __fmul_rn(__fsub_rn(bx2, bx1), __fsub_rn(by2, by1));
        float den = __fsub_rn(__fadd_rn(area_g, area_b), inter);
        iou = __fdiv_rn(inter, den);
    }
    // gather the 9 ious in rank order on every lane
    float iouk[KK];
#pragma unroll
    for (int k = 0; k < KK; k++) iouk[k] = __shfl_sync(FULL, iou, k);
    // mean + std (ddof=1), identical sequential f32 on all lanes
    float s = 0.0f;
#pragma unroll
    for (int k = 0; k < KK; k++) s = __fadd_rn(s, iouk[k]);
    float mean = __fdiv_rn(s, 9.0f);
    float vv = 0.0f;
#pragma unroll
    for (int k = 0; k < KK; k++) {
        float cdev = __fsub_rn(iouk[k], mean);
        vv = __fadd_rn(vv, __fmul_rn(cdev, cdev));
    }
    float thr = __fadd_rn(mean, __fsqrt_rn(__fdiv_rn(vv, 8.0f)));

    if (lane < KK) {
        bool inside = (gx1 <= cx) && (cx <= gx2) && (gy1 <= cy) && (cy <= gy2);
        bool msk = (iou >= thr) && inside;
        const size_t S = (size_t)B_ * G_ * KK;
        const size_t base = ((size_t)img * G_ + g) * KK + lane;
        out[base]         = msk ? (float)myidx : -1.0f;
        out[S + base]     = msk ? (float)g : -1.0f;
        out[2 * S + base] = msk ? 1.0f : 0.0f;
        out[3 * S + base] = iou;
    }
}

extern "C" void kernel_launch(void* const* d_in, const int* in_sizes, int n_in,
                              void* d_out, int out_size) {
    const float* pred = (const float*)d_in[0];  // [16,30000,4]
    const float* gt   = (const float*)d_in[1];  // [16,64,4]
    float* out = (float*)d_out;
    atss_compact<<<B_ * 16, 512>>>(pred, gt);                 // 256 blocks
    atss_assign<<<(B_ * G_) / 16, 512>>>(pred, gt, out);      // 64 blocks
}

// round 6
// speedup vs baseline: 13.7311x; 1.1664x over previous
#include <cuda_runtime.h>
#include <cstdint>

// ATSS: B=16, N=30000, G=64, K=9.
// Out (float), tuple order, each [B,G,K], S=9216:
//   [0,S) pred_idx | [S,2S) gt_idx | [2S,3S) mask | [3S,4S) ious

#define B_ 16
#define N_ 30000
#define G_ 64
#define KK 9
#define FULL 0xffffffffu
#define CAP 256
#define SLICE (N_ / 16)        // 1875 preds per compact block

// Radius pre-filter (uniform data: 9th-NN ~0.0098; r=0.04 -> ~150 cands/GT).
// Correctness never depends on it: certificate + inline exact fallback.
#define RADIUS 0.04f
#define R2G   (RADIUS * RADIUS * 1.000002f)   // compaction guard (covers fma err)
#define R2CHK (RADIUS * RADIUS * 0.999998f)   // certificate bound on exact d9^2

__device__ int    d_cnt[B_ * G_];                 // zeroed at load; self-reset
__device__ float4 d_rec[B_ * G_ * CAP];           // (cx, cy, bitcast idx, -)

__device__ __forceinline__ float f_inf() { return __int_as_float(0x7f800000); }

// ---------------- Phase A: candidate compaction ----------------
__global__ __launch_bounds__(512) void atss_compact(
    const float* __restrict__ pred, const float* __restrict__ gt)
{
    const int img   = blockIdx.x >> 4;
    const int slice = blockIdx.x & 15;

    __shared__ float2 sg[G_];
    if (threadIdx.x < G_) {
        float4 q = reinterpret_cast<const float4*>(gt)[img * G_ + threadIdx.x];
        sg[threadIdx.x] = make_float2(q.x, q.y);
    }
    __syncthreads();

    const float4* __restrict__ pb = reinterpret_cast<const float4*>(pred) + (size_t)img * N_;
    const int sbeg = slice * SLICE;

    // Register-tile 4 preds per thread (coalesced float4 loads, MLP=4).
    float px[4], py[4]; int pi[4]; bool pv[4];
#pragma unroll
    for (int q = 0; q < 4; q++) {
        int i = sbeg + (int)threadIdx.x + q * 512;
        pv[q] = (i < sbeg + SLICE);
        pi[q] = i;
        float4 p = pb[pv[q] ? i : sbeg];
        px[q] = p.x; py[q] = p.y;
    }

    unsigned m0[4] = {0, 0, 0, 0}, m1[4] = {0, 0, 0, 0};
#pragma unroll 8
    for (int j = 0; j < G_; j++) {
        float2 gxy = sg[j];
        unsigned lo = (j < 32) ? (1u << j) : 0u;
        unsigned hi = (j < 32) ? 0u : (1u << (j - 32));
#pragma unroll
        for (int q = 0; q < 4; q++) {
            float dx = gxy.x - px[q], dy = gxy.y - py[q];
            bool hit = __fmaf_rn(dx, dx, dy * dy) <= R2G;
            if (hit) { m0[q] |= lo; m1[q] |= hi; }
        }
    }
#pragma unroll
    for (int q = 0; q < 4; q++) {
        if (!pv[q]) continue;
        unsigned a = m0[q];
        while (a) {
            int g = __ffs(a) - 1; a &= a - 1;
            int pos = atomicAdd(&d_cnt[img * G_ + g], 1);
            if (pos < CAP)
                d_rec[(img * G_ + g) * CAP + pos] =
                    make_float4(px[q], py[q], __int_as_float(pi[q]), 0.0f);
        }
        unsigned b = m1[q];
        while (b) {
            int g = __ffs(b) + 31; b &= b - 1;
            int pos = atomicAdd(&d_cnt[img * G_ + g], 1);
            if (pos < CAP)
                d_rec[(img * G_ + g) * CAP + pos] =
                    make_float4(px[q], py[q], __int_as_float(pi[q]), 0.0f);
        }
    }
}

// Lane-distributed sorted top-9 insertion (fallback path only).
__device__ __forceinline__ void insert_batch(
    float de, int idx, bool v, float& ldv, int& liv, int lane)
{
    float d8 = __shfl_sync(FULL, ldv, 8);
    int   i8 = __shfl_sync(FULL, liv, 8);
    bool qq = v && ((de < d8) || (de == d8 && idx < i8));
    unsigned m = __ballot_sync(FULL, qq);
    while (m) {
        int src = __ffs(m) - 1; m &= m - 1;
        float dv = __shfl_sync(FULL, de, src);
        int   iv = __shfl_sync(FULL, idx, src);
        bool ogt = (ldv > dv) || (ldv == dv && liv > iv);
        unsigned bgt = __ballot_sync(FULL, ogt);
        int pos = __popc(~bgt & 0x1FFu);
        float pd = __shfl_up_sync(FULL, ldv, 1);
        int   pi2 = __shfl_up_sync(FULL, liv, 1);
        if (lane <= 8) {
            if (lane == pos)     { ldv = dv; liv = iv; }
            else if (lane > pos) { ldv = pd; liv = pi2; }
        }
    }
}

#define CE(a, b)                                                            \
    { bool sw = (ed[a] > ed[b]) || (ed[a] == ed[b] && ei[a] > ei[b]);       \
      float td = sw ? ed[b] : ed[a]; ed[b] = sw ? ed[a] : ed[b]; ed[a] = td;\
      int   ti = sw ? ei[b] : ei[a]; ei[b] = sw ? ei[a] : ei[b]; ei[a] = ti; }

// ---------------- Phase B: per-GT top-9 + epilogue ----------------
__global__ __launch_bounds__(128) void atss_assign(
    const float* __restrict__ pred, const float* __restrict__ gt,
    float* __restrict__ out)
{
    const int warp = (blockIdx.x << 2) + (threadIdx.x >> 5);  // 0..1023
    const int img  = warp >> 6;
    const int g    = warp & 63;
    const int lane = threadIdx.x & 31;

    const float4* __restrict__ pb  = reinterpret_cast<const float4*>(pred) + (size_t)img * N_;
    const float2* __restrict__ pb2 = reinterpret_cast<const float2*>(pred) + (size_t)img * N_ * 2;
    float4 qg = reinterpret_cast<const float4*>(gt)[img * G_ + g];

    int c = d_cnt[img * G_ + g];
    if (lane == 0) d_cnt[img * G_ + g] = 0;      // self-reset for graph replay
    const float4* __restrict__ rec = &d_rec[(img * G_ + g) * CAP];

    int myidx = 0x7fffffff;
    bool ok = (c >= KK && c <= CAP);
    if (ok) {
        // Per-lane <=8 candidates, coalesced LDG.128 streams.
        float ed[8]; int ei[8];
#pragma unroll
        for (int q = 0; q < 8; q++) {
            int k = lane + q * 32;
            bool v = k < c;
            float4 r = rec[v ? k : 0];
            // Exact distance matching JAX: rn sub/mul/add then IEEE sqrt.
            float dx = __fsub_rn(qg.x, r.x), dy = __fsub_rn(qg.y, r.y);
            float de = __fsqrt_rn(__fadd_rn(__fmul_rn(dx, dx), __fmul_rn(dy, dy)));
            ed[q] = v ? de : f_inf();
            ei[q] = v ? __float_as_int(r.z) : 0x7fffffff;
        }
        // Batcher 8-sorter (19 CEs, static indices, asc by (d, idx)).
        CE(0,1) CE(2,3) CE(4,5) CE(6,7)
        CE(0,2) CE(1,3) CE(4,6) CE(5,7)
        CE(1,2) CE(5,6)
        CE(0,4) CE(1,5) CE(2,6) CE(3,7)
        CE(2,4) CE(3,5)
        CE(1,2) CE(3,4) CE(5,6)

        // 9 selection rounds via hardware REDUX (d>=0 -> uint-monotone).
        unsigned lastd = 0; int lasti = 0x7fffffff;
        for (int r = 0; r < KK; r++) {
            unsigned db = __float_as_uint(ed[0]);
            unsigned mn = __reduce_min_sync(FULL, db);
            bool match = (db == mn);
            unsigned imn = __reduce_min_sync(FULL, match ? (unsigned)ei[0] : 0x7fffffffu);
            if (lane == r) myidx = (int)imn;
            lastd = mn; lasti = (int)imn;
            bool win = match && ((unsigned)ei[0] == imn);
            if (win) {
#pragma unroll
                for (int q = 0; q < 7; q++) { ed[q] = ed[q + 1]; ei[q] = ei[q + 1]; }
                ed[7] = f_inf(); ei[7] = 0x7fffffff;
            }
        }
        float d8 = __uint_as_float(lastd);
        // Certificate: excluded preds provably have d^2 > R2CHK.
        ok = (lasti != 0x7fffffff) && (__fmul_rn(d8, d8) < R2CHK);
    }
    if (!ok) {   // exact full scan (deterministic, identical arithmetic)
        float ldv = f_inf(); int liv = 0x7fffffff;
        for (int b = 0; b < N_; b += 32) {
            int idx = b + lane; bool v = idx < N_;
            float2 p = pb2[2 * (v ? idx : 0)];
            float dx = __fsub_rn(qg.x, p.x), dy = __fsub_rn(qg.y, p.y);
            float de = __fsqrt_rn(__fadd_rn(__fmul_rn(dx, dx), __fmul_rn(dy, dy)));
            insert_batch(de, idx, v, ldv, liv, lane);
        }
        myidx = liv;   // lanes 0..8 hold ranks 0..8
    }

    // ---- epilogue: lanes 0..8 in parallel, exact rn ops ----
    float ghw = __fmul_rn(0.5f, qg.z), ghh = __fmul_rn(0.5f, qg.w);
    float gx1 = __fsub_rn(qg.x, ghw), gy1 = __fsub_rn(qg.y, ghh);
    float gx2 = __fadd_rn(qg.x, ghw), gy2 = __fadd_rn(qg.y, ghh);
    float area_g = __fmul_rn(__fsub_rn(gx2, gx1), __fsub_rn(gy2, gy1));

    float iou = 0.0f, cx = 0.0f, cy = 0.0f;
    if (lane < KK) {
        float4 p = pb[myidx];
        cx = p.x; cy = p.y;
        float hw = __fmul_rn(0.5f, p.z), hh = __fmul_rn(0.5f, p.w);
        float bx1 = __fsub_rn(p.x, hw), by1 = __fsub_rn(p.y, hh);
        float bx2 = __fadd_rn(p.x, hw), by2 = __fadd_rn(p.y, hh);
        float ltx = fmaxf(gx1, bx1), lty = fmaxf(gy1, by1);
        float rbx = fminf(gx2, bx2), rby = fminf(gy2, by2);
        float wd = fmaxf(__fsub_rn(rbx, ltx), 0.0f);
        float ht = fmaxf(__fsub_rn(rby, lty), 0.0f);
        float inter = __fmul_rn(wd, ht);
        float area_b = __fmul_rn(__fsub_rn(bx2, bx1), __fsub_rn(by2, by1));
        float den = __fsub_rn(__fadd_rn(area_g, area_b), inter);
        iou = __fdiv_rn(inter, den);
    }
    float iouk[KK];
#pragma unroll
    for (int k = 0; k < KK; k++) iouk[k] = __shfl_sync(FULL, iou, k);
    float s = 0.0f;
#pragma unroll
    for (int k = 0; k < KK; k++) s = __fadd_rn(s, iouk[k]);
    float mean = __fdiv_rn(s, 9.0f);
    float vv = 0.0f;
#pragma unroll
    for (int k = 0; k < KK; k++) {
        float cdev = __fsub_rn(iouk[k], mean);
        vv = __fadd_rn(vv, __fmul_rn(cdev, cdev));
    }
    float thr = __fadd_rn(mean, __fsqrt_rn(__fdiv_rn(vv, 8.0f)));

    if (lane < KK) {
        bool inside = (gx1 <= cx) && (cx <= gx2) && (gy1 <= cy) && (cy <= gy2);
        bool msk = (iou >= thr) && inside;
        const size_t S = (size_t)B_ * G_ * KK;
        const size_t base = ((size_t)img * G_ + g) * KK + lane;
        out[base]         = msk ? (float)myidx : -1.0f;
        out[S + base]     = msk ? (float)g : -1.0f;
        out[2 * S + base] = msk ? 1.0f : 0.0f;
        out[3 * S + base] = iou;
    }
}

extern "C" void kernel_launch(void* const* d_in, const int* in_sizes, int n_in,
                              void* d_out, int out_size) {
    const float* pred = (const float*)d_in[0];  // [16,30000,4]
    const float* gt   = (const float*)d_in[1];  // [16,64,4]
    float* out = (float*)d_out;
    atss_compact<<<B_ * 16, 512>>>(pred, gt);                 // 256 blocks
    atss_assign<<<(B_ * G_) / 4, 128>>>(pred, gt, out);       // 256 blocks
}